// round 1
// baseline (speedup 1.0000x reference)
#include <cuda_runtime.h>
#include <math.h>

#define N_NODES 100000
#define D 64
#define E_MAX 1600000
#define CHUNK 1024
#define NCHUNK ((N_NODES + CHUNK - 1) / CHUNK)   // 98

// ---- scratch (static __device__ globals: allocation-free per harness rules) ----
__device__ float g_bufA[(size_t)N_NODES * D];   // GEMM output (messages m)
__device__ float g_bufB[(size_t)N_NODES * D];   // aggregation output (h)
__device__ float g_r[N_NODES];                  // per-node scalar for layer-3 collapse
__device__ int   g_cnt[N_NODES];                // in-degree per node
__device__ int   g_rowptr[N_NODES];             // CSR row starts (by dst)
__device__ int   g_cursor[N_NODES];             // fill cursors
__device__ int   g_eidx[E_MAX];                 // CSR: src index per incoming edge
__device__ int   g_csum[128];                   // chunk sums for scan
__device__ int   g_coff[128];                   // chunk offsets

// ============================ CSR build ============================

__global__ void zero_cnt_kernel() {
    int i = blockIdx.x * blockDim.x + threadIdx.x;
    if (i < N_NODES) g_cnt[i] = 0;
}

__global__ void degree_kernel(const int* __restrict__ dst, int E) {
    int e = blockIdx.x * blockDim.x + threadIdx.x;
    if (e < E) atomicAdd(&g_cnt[dst[e]], 1);
}

// per-chunk reduce: csum[b] = sum of cnt in chunk b (256 thr, 4 elems/thr)
__global__ void chunk_reduce_kernel() {
    int base = blockIdx.x * CHUNK + threadIdx.x * 4;
    int s = 0;
#pragma unroll
    for (int i = 0; i < 4; i++) {
        int idx = base + i;
        if (idx < N_NODES) s += g_cnt[idx];
    }
#pragma unroll
    for (int off = 16; off; off >>= 1) s += __shfl_down_sync(0xffffffffu, s, off);
    __shared__ int ws[8];
    if ((threadIdx.x & 31) == 0) ws[threadIdx.x >> 5] = s;
    __syncthreads();
    if (threadIdx.x == 0) {
        int t = 0;
#pragma unroll
        for (int i = 0; i < 8; i++) t += ws[i];
        g_csum[blockIdx.x] = t;
    }
}

// single-block exclusive scan over chunk sums (<=128 chunks)
__global__ void chunk_scan_kernel(int nchunk) {
    __shared__ int sm[128];
    int t = threadIdx.x;  // 128 threads
    int v = (t < nchunk) ? g_csum[t] : 0;
    sm[t] = v;
    __syncthreads();
    for (int d = 1; d < 128; d <<= 1) {
        int add = (t >= d) ? sm[t - d] : 0;
        __syncthreads();
        sm[t] += add;
        __syncthreads();
    }
    if (t < nchunk) g_coff[t] = sm[t] - v;  // exclusive
}

// per-chunk exclusive scan + offset -> rowptr & cursor
__global__ void chunk_apply_kernel() {
    int t = threadIdx.x;  // 256 threads
    int base = blockIdx.x * CHUNK + t * 4;
    int c[4];
    int ts = 0;
#pragma unroll
    for (int i = 0; i < 4; i++) {
        int idx = base + i;
        c[i] = (idx < N_NODES) ? g_cnt[idx] : 0;
        ts += c[i];
    }
    int lane = t & 31, wid = t >> 5;
    int incl = ts;
#pragma unroll
    for (int d = 1; d < 32; d <<= 1) {
        int u = __shfl_up_sync(0xffffffffu, incl, d);
        if (lane >= d) incl += u;
    }
    __shared__ int wsum[8];
    __shared__ int woff[8];
    if (lane == 31) wsum[wid] = incl;
    __syncthreads();
    if (t == 0) {
        int acc = 0;
#pragma unroll
        for (int i = 0; i < 8; i++) { woff[i] = acc; acc += wsum[i]; }
    }
    __syncthreads();
    int excl = incl - ts + woff[wid] + g_coff[blockIdx.x];
#pragma unroll
    for (int i = 0; i < 4; i++) {
        int idx = base + i;
        if (idx < N_NODES) { g_rowptr[idx] = excl; g_cursor[idx] = excl; }
        excl += c[i];
    }
}

__global__ void fill_kernel(const int* __restrict__ src, const int* __restrict__ dst, int E) {
    int e = blockIdx.x * blockDim.x + threadIdx.x;
    if (e < E) {
        int pos = atomicAdd(&g_cursor[dst[e]], 1);
        g_eidx[pos] = src[e];
    }
}

// ============================ compute kernels ============================

// out[row] = in[row] @ W^T + b   (W row-major [j][k], out[row][j] = sum_k in[row][k]*W[j][k] + b[j])
__global__ __launch_bounds__(128) void gemm_kernel(const float* __restrict__ in,
                                                   const float* __restrict__ W,
                                                   const float* __restrict__ b,
                                                   float* __restrict__ out) {
    __shared__ float Ws[D * D];
    __shared__ float bs[D];
    int t = threadIdx.x;  // 128
    for (int i = t; i < D * D; i += 128) Ws[i] = W[i];
    if (t < D) bs[t] = b[t];
    __syncthreads();
    int row = blockIdx.x * 128 + t;
    if (row >= N_NODES) return;

    float4 h[16];
    const float4* inr = reinterpret_cast<const float4*>(in + (size_t)row * D);
#pragma unroll
    for (int i = 0; i < 16; i++) h[i] = inr[i];

    float4* outr = reinterpret_cast<float4*>(out + (size_t)row * D);
#pragma unroll
    for (int j4 = 0; j4 < 16; j4++) {
        float a0 = bs[j4 * 4 + 0], a1 = bs[j4 * 4 + 1], a2 = bs[j4 * 4 + 2], a3 = bs[j4 * 4 + 3];
        const float4* w0 = reinterpret_cast<const float4*>(Ws + (j4 * 4 + 0) * D);
        const float4* w1 = reinterpret_cast<const float4*>(Ws + (j4 * 4 + 1) * D);
        const float4* w2 = reinterpret_cast<const float4*>(Ws + (j4 * 4 + 2) * D);
        const float4* w3 = reinterpret_cast<const float4*>(Ws + (j4 * 4 + 3) * D);
#pragma unroll
        for (int kk = 0; kk < 16; kk++) {
            float4 hv = h[kk];
            float4 v0 = w0[kk], v1 = w1[kk], v2 = w2[kk], v3 = w3[kk];
            a0 += hv.x * v0.x + hv.y * v0.y + hv.z * v0.z + hv.w * v0.w;
            a1 += hv.x * v1.x + hv.y * v1.y + hv.z * v1.z + hv.w * v1.w;
            a2 += hv.x * v2.x + hv.y * v2.y + hv.z * v2.z + hv.w * v2.w;
            a3 += hv.x * v3.x + hv.y * v3.y + hv.z * v3.z + hv.w * v3.w;
        }
        outr[j4] = make_float4(a0, a1, a2, a3);
    }
}

// CSR gather aggregation: out[i] = (tanh of) sum over incoming edges of m[src]
// one warp per node; lane l owns feature cols l and l+32 (coalesced 2x128B per edge row)
__global__ __launch_bounds__(256) void agg_kernel(const float* __restrict__ m,
                                                  float* __restrict__ out,
                                                  int applyTanh) {
    int warpId = (blockIdx.x * blockDim.x + threadIdx.x) >> 5;
    int l = threadIdx.x & 31;
    if (warpId >= N_NODES) return;
    int start = g_rowptr[warpId];
    int n = g_cnt[warpId];
    float a0 = 0.f, a1 = 0.f;
    for (int base = 0; base < n; base += 32) {
        int myE = (base + l < n) ? g_eidx[start + base + l] : 0;
        int lim = min(32, n - base);
        for (int k = 0; k < lim; k++) {
            int s = __shfl_sync(0xffffffffu, myE, k);
            const float* row = m + (size_t)s * D;
            a0 += __ldg(row + l);
            a1 += __ldg(row + l + 32);
        }
    }
    if (applyTanh) { a0 = tanhf(a0); a1 = tanhf(a1); }
    out[(size_t)warpId * D + l] = a0;
    out[(size_t)warpId * D + 32 + l] = a1;
}

// layer-3 collapse: r[i] = h[i] . colsum(W3) + sum(b3)
__global__ __launch_bounds__(128) void rsum_kernel(const float* __restrict__ h,
                                                   const float* __restrict__ W3,
                                                   const float* __restrict__ b3) {
    __shared__ float ws[D];
    __shared__ float bsum;
    int t = threadIdx.x;  // 128
    if (t < D) {
        float s = 0.f;
#pragma unroll
        for (int j = 0; j < D; j++) s += W3[j * D + t];
        ws[t] = s;
    }
    if (t == 0) {
        float s = 0.f;
#pragma unroll
        for (int j = 0; j < D; j++) s += b3[j];
        bsum = s;
    }
    __syncthreads();
    for (int row = blockIdx.x * blockDim.x + t; row < N_NODES; row += gridDim.x * blockDim.x) {
        const float4* hr = reinterpret_cast<const float4*>(h + (size_t)row * D);
        float acc = bsum;
#pragma unroll
        for (int kk = 0; kk < 16; kk++) {
            float4 v = hr[kk];
            acc += v.x * ws[kk * 4 + 0] + v.y * ws[kk * 4 + 1] +
                   v.z * ws[kk * 4 + 2] + v.w * ws[kk * 4 + 3];
        }
        g_r[row] = acc;
    }
}

// final: per node, sum r over incoming edges; segment-sum by graph with
// block-shared accumulators; 8 global atomics per block.
__global__ __launch_bounds__(256) void final_kernel(const int* __restrict__ n2g,
                                                    float* __restrict__ out) {
    __shared__ float acc8[8];
    int t = threadIdx.x;
    if (t < 8) acc8[t] = 0.f;
    __syncthreads();
    int l = t & 31;
    int w = t >> 5;
    int warpsPerGrid = (gridDim.x * blockDim.x) >> 5;
    for (int i = blockIdx.x * (blockDim.x >> 5) + w; i < N_NODES; i += warpsPerGrid) {
        int start = g_rowptr[i], n = g_cnt[i];
        float s = 0.f;
        for (int e = l; e < n; e += 32) s += g_r[g_eidx[start + e]];
#pragma unroll
        for (int off = 16; off; off >>= 1) s += __shfl_down_sync(0xffffffffu, s, off);
        if (l == 0) atomicAdd(&acc8[n2g[i]], s);
    }
    __syncthreads();
    if (t < 8) atomicAdd(&out[t], acc8[t]);
}

// ============================ launch ============================

extern "C" void kernel_launch(void* const* d_in, const int* in_sizes, int n_in,
                              void* d_out, int out_size) {
    const float* x   = (const float*)d_in[0];
    const float* W1  = (const float*)d_in[1];
    const float* b1  = (const float*)d_in[2];
    const float* W2  = (const float*)d_in[3];
    const float* b2  = (const float*)d_in[4];
    const float* W3  = (const float*)d_in[5];
    const float* b3  = (const float*)d_in[6];
    const int*   src = (const int*)d_in[7];
    const int*   dst = (const int*)d_in[8];
    const int*   n2g = (const int*)d_in[9];
    float* out = (float*)d_out;

    int E = in_sizes[7];

    int nb_nodes = (N_NODES + 255) / 256;
    int nb_edges = (E + 255) / 256;

    // --- CSR build (by dst) ---
    zero_cnt_kernel<<<nb_nodes, 256>>>();
    degree_kernel<<<nb_edges, 256>>>(dst, E);
    chunk_reduce_kernel<<<NCHUNK, 256>>>();
    chunk_scan_kernel<<<1, 128>>>(NCHUNK);
    chunk_apply_kernel<<<NCHUNK, 256>>>();
    fill_kernel<<<nb_edges, 256>>>(src, dst, E);

    int gemm_blocks = (N_NODES + 127) / 128;
    int agg_blocks = (N_NODES * 32 + 255) / 256;

    // --- layer 1 ---
    gemm_kernel<<<gemm_blocks, 128>>>(x, W1, b1, g_bufA);
    agg_kernel<<<agg_blocks, 256>>>(g_bufA, g_bufB, 1);
    // --- layer 2 ---
    gemm_kernel<<<gemm_blocks, 128>>>(g_bufB, W2, b2, g_bufA);
    agg_kernel<<<agg_blocks, 256>>>(g_bufA, g_bufB, 1);
    // --- layer 3 collapsed to scalar per node ---
    rsum_kernel<<<512, 128>>>(g_bufB, W3, b3);
    cudaMemsetAsync(d_out, 0, (size_t)out_size * sizeof(float));
    final_kernel<<<296, 256>>>(n2g, out);
}

// round 2
// speedup vs baseline: 15.4915x; 15.4915x over previous
#include <cuda_runtime.h>
#include <math.h>

#define N_NODES 100000
#define D 64

// ---- scratch (__device__ globals: allocation-free per harness rules) ----
__device__ float g_bufA[(size_t)N_NODES * D];   // GEMM output (messages m)
__device__ float g_bufB[(size_t)N_NODES * D];   // scatter-aggregation output
__device__ float g_r[N_NODES];                  // per-node scalar (layer-3 collapse)

// ============================ kernels ============================

// out[row] = (tanh? tanh(in[row]) : in[row]) @ W^T + b
// W row-major [j][k]; out[row][j] = sum_k in_k * W[j][k] + b[j]
__global__ __launch_bounds__(128) void gemm_kernel(const float* __restrict__ in,
                                                   const float* __restrict__ W,
                                                   const float* __restrict__ b,
                                                   float* __restrict__ out,
                                                   int tanhIn) {
    __shared__ float Ws[D * D];
    __shared__ float bs[D];
    int t = threadIdx.x;  // 128
    for (int i = t; i < D * D; i += 128) Ws[i] = W[i];
    if (t < D) bs[t] = b[t];
    __syncthreads();
    int row = blockIdx.x * 128 + t;
    if (row >= N_NODES) return;

    float4 h[16];
    const float4* inr = reinterpret_cast<const float4*>(in + (size_t)row * D);
#pragma unroll
    for (int i = 0; i < 16; i++) h[i] = inr[i];
    if (tanhIn) {
#pragma unroll
        for (int i = 0; i < 16; i++) {
            h[i].x = tanhf(h[i].x); h[i].y = tanhf(h[i].y);
            h[i].z = tanhf(h[i].z); h[i].w = tanhf(h[i].w);
        }
    }

    float4* outr = reinterpret_cast<float4*>(out + (size_t)row * D);
#pragma unroll
    for (int j4 = 0; j4 < 16; j4++) {
        float a0 = bs[j4 * 4 + 0], a1 = bs[j4 * 4 + 1], a2 = bs[j4 * 4 + 2], a3 = bs[j4 * 4 + 3];
        const float4* w0 = reinterpret_cast<const float4*>(Ws + (j4 * 4 + 0) * D);
        const float4* w1 = reinterpret_cast<const float4*>(Ws + (j4 * 4 + 1) * D);
        const float4* w2 = reinterpret_cast<const float4*>(Ws + (j4 * 4 + 2) * D);
        const float4* w3 = reinterpret_cast<const float4*>(Ws + (j4 * 4 + 3) * D);
#pragma unroll
        for (int kk = 0; kk < 16; kk++) {
            float4 hv = h[kk];
            float4 v0 = w0[kk], v1 = w1[kk], v2 = w2[kk], v3 = w3[kk];
            a0 += hv.x * v0.x + hv.y * v0.y + hv.z * v0.z + hv.w * v0.w;
            a1 += hv.x * v1.x + hv.y * v1.y + hv.z * v1.z + hv.w * v1.w;
            a2 += hv.x * v2.x + hv.y * v2.y + hv.z * v2.z + hv.w * v2.w;
            a3 += hv.x * v3.x + hv.y * v3.y + hv.z * v3.z + hv.w * v3.w;
        }
        outr[j4] = make_float4(a0, a1, a2, a3);
    }
}

// vectorized fire-and-forget reduction (sm_90+): out[0..3] += v
__device__ __forceinline__ void red_add_v4(float* p, float4 v) {
    asm volatile("red.global.add.v4.f32 [%0], {%1, %2, %3, %4};"
                 :: "l"(p), "f"(v.x), "f"(v.y), "f"(v.z), "f"(v.w) : "memory");
}

// edge-parallel scatter: out[dst[e]] += m[src[e]]  (64 floats/edge)
// 4 threads per edge; each thread handles 16 contiguous floats (4 x float4).
__global__ __launch_bounds__(256) void scatter_kernel(const float* __restrict__ m,
                                                      const int* __restrict__ src,
                                                      const int* __restrict__ dst,
                                                      float* __restrict__ out, int E) {
    int tid = blockIdx.x * blockDim.x + threadIdx.x;
    int e = tid >> 2, q = tid & 3;
    if (e >= E) return;
    int s = __ldg(src + e);
    int d = __ldg(dst + e);
    const float4* in = reinterpret_cast<const float4*>(m + (size_t)s * D) + q * 4;
    float* op = out + (size_t)d * D + q * 16;
    float4 v0 = __ldg(in + 0);
    float4 v1 = __ldg(in + 1);
    float4 v2 = __ldg(in + 2);
    float4 v3 = __ldg(in + 3);
    red_add_v4(op + 0,  v0);
    red_add_v4(op + 4,  v1);
    red_add_v4(op + 8,  v2);
    red_add_v4(op + 12, v3);
}

// layer-3 collapse: r[i] = tanh(h[i]) . colsum(W3) + sum(b3)
__global__ __launch_bounds__(128) void rsum_kernel(const float* __restrict__ h,
                                                   const float* __restrict__ W3,
                                                   const float* __restrict__ b3) {
    __shared__ float ws[D];
    __shared__ float bsum;
    int t = threadIdx.x;  // 128
    if (t < D) {
        float s = 0.f;
#pragma unroll
        for (int j = 0; j < D; j++) s += W3[j * D + t];
        ws[t] = s;
    }
    if (t == 0) {
        float s = 0.f;
#pragma unroll
        for (int j = 0; j < D; j++) s += b3[j];
        bsum = s;
    }
    __syncthreads();
    for (int row = blockIdx.x * blockDim.x + t; row < N_NODES; row += gridDim.x * blockDim.x) {
        const float4* hr = reinterpret_cast<const float4*>(h + (size_t)row * D);
        float acc = bsum;
#pragma unroll
        for (int kk = 0; kk < 16; kk++) {
            float4 v = hr[kk];
            acc += tanhf(v.x) * ws[kk * 4 + 0] + tanhf(v.y) * ws[kk * 4 + 1] +
                   tanhf(v.z) * ws[kk * 4 + 2] + tanhf(v.w) * ws[kk * 4 + 3];
        }
        g_r[row] = acc;
    }
}

// final: out[g] = sum over edges of r[src[e]] where graph(dst[e]) == g
__global__ __launch_bounds__(256) void final_kernel(const int* __restrict__ src,
                                                    const int* __restrict__ dst,
                                                    const int* __restrict__ n2g,
                                                    float* __restrict__ out, int E) {
    __shared__ float bins[8];
    int t = threadIdx.x;
    if (t < 8) bins[t] = 0.f;
    __syncthreads();
    int e = blockIdx.x * blockDim.x + t;
    if (e < E) {
        float v = __ldg(g_r + __ldg(src + e));
        int g = __ldg(n2g + __ldg(dst + e));
        atomicAdd(&bins[g], v);
    }
    __syncthreads();
    if (t < 8) atomicAdd(&out[t], bins[t]);
}

// ============================ launch ============================

extern "C" void kernel_launch(void* const* d_in, const int* in_sizes, int n_in,
                              void* d_out, int out_size) {
    const float* x   = (const float*)d_in[0];
    const float* W1  = (const float*)d_in[1];
    const float* b1  = (const float*)d_in[2];
    const float* W2  = (const float*)d_in[3];
    const float* b2  = (const float*)d_in[4];
    const float* W3  = (const float*)d_in[5];
    const float* b3  = (const float*)d_in[6];
    const int*   src = (const int*)d_in[7];
    const int*   dst = (const int*)d_in[8];
    const int*   n2g = (const int*)d_in[9];
    float* out = (float*)d_out;

    int E = in_sizes[7];

    int gemm_blocks = (N_NODES + 127) / 128;
    int scat_blocks = (E * 4 + 255) / 256;
    int fin_blocks  = (E + 255) / 256;

    // resolve device-global addresses (host-side, done every call; cheap)
    float *bufA, *bufB;
    cudaGetSymbolAddress((void**)&bufA, g_bufA);
    cudaGetSymbolAddress((void**)&bufB, g_bufB);

    // layer 1:  A = x @ W1^T + b1 ; B = scatter(A)
    cudaMemsetAsync(bufB, 0, (size_t)N_NODES * D * sizeof(float));
    gemm_kernel<<<gemm_blocks, 128>>>(x, W1, b1, bufA, 0);
    scatter_kernel<<<scat_blocks, 256>>>(bufA, src, dst, bufB, E);
    // layer 2:  A = tanh(B) @ W2^T + b2 ; B = scatter(A)
    gemm_kernel<<<gemm_blocks, 128>>>(bufB, W2, b2, bufA, 1);
    cudaMemsetAsync(bufB, 0, (size_t)N_NODES * D * sizeof(float));
    scatter_kernel<<<scat_blocks, 256>>>(bufA, src, dst, bufB, E);
    // layer 3 collapsed: r[i] = tanh(B[i]) . colsum(W3) + sum(b3)
    rsum_kernel<<<512, 128>>>(bufB, W3, b3);
    // per-graph reduction over edges
    cudaMemsetAsync(d_out, 0, (size_t)out_size * sizeof(float));
    final_kernel<<<fin_blocks, 256>>>(src, dst, n2g, out, E);
}

// round 3
// speedup vs baseline: 23.5384x; 1.5194x over previous
#include <cuda_runtime.h>
#include <math.h>

#define N_NODES 100000
#define D 64
#define E_MAX 1600000
#define CHUNK 1024
#define NCHUNK ((N_NODES + CHUNK - 1) / CHUNK)   // 98

// ---- scratch (__device__ globals: allocation-free per harness rules) ----
__device__ float g_bufA[(size_t)N_NODES * D];
__device__ float g_bufB[(size_t)N_NODES * D];
__device__ float g_r[N_NODES];
__device__ float g_ws[D];       // colsum(W3)
__device__ float g_bsum[1];     // sum(b3)
__device__ int   g_cnt[N_NODES];
__device__ int   g_rowptr[N_NODES];
__device__ int   g_cursor[N_NODES];
__device__ int   g_eidx[E_MAX];
__device__ int   g_csum[128];
__device__ int   g_coff[128];

// ============================ CSR build ============================

__global__ void zero_cnt_kernel() {
    int i = blockIdx.x * blockDim.x + threadIdx.x;
    if (i < N_NODES) g_cnt[i] = 0;
}

__global__ void degree_kernel(const int* __restrict__ dst, int E) {
    int e = blockIdx.x * blockDim.x + threadIdx.x;
    if (e < E) atomicAdd(&g_cnt[dst[e]], 1);   // no return -> REDG
}

__global__ void chunk_reduce_kernel() {
    int base = blockIdx.x * CHUNK + threadIdx.x * 4;
    int s = 0;
#pragma unroll
    for (int i = 0; i < 4; i++) {
        int idx = base + i;
        if (idx < N_NODES) s += g_cnt[idx];
    }
#pragma unroll
    for (int off = 16; off; off >>= 1) s += __shfl_down_sync(0xffffffffu, s, off);
    __shared__ int ws[8];
    if ((threadIdx.x & 31) == 0) ws[threadIdx.x >> 5] = s;
    __syncthreads();
    if (threadIdx.x == 0) {
        int t = 0;
#pragma unroll
        for (int i = 0; i < 8; i++) t += ws[i];
        g_csum[blockIdx.x] = t;
    }
}

__global__ void chunk_scan_kernel(int nchunk) {
    __shared__ int sm[128];
    int t = threadIdx.x;
    int v = (t < nchunk) ? g_csum[t] : 0;
    sm[t] = v;
    __syncthreads();
    for (int d = 1; d < 128; d <<= 1) {
        int add = (t >= d) ? sm[t - d] : 0;
        __syncthreads();
        sm[t] += add;
        __syncthreads();
    }
    if (t < nchunk) g_coff[t] = sm[t] - v;
}

__global__ void chunk_apply_kernel() {
    int t = threadIdx.x;  // 256
    int base = blockIdx.x * CHUNK + t * 4;
    int c[4];
    int ts = 0;
#pragma unroll
    for (int i = 0; i < 4; i++) {
        int idx = base + i;
        c[i] = (idx < N_NODES) ? g_cnt[idx] : 0;
        ts += c[i];
    }
    int lane = t & 31, wid = t >> 5;
    int incl = ts;
#pragma unroll
    for (int d = 1; d < 32; d <<= 1) {
        int u = __shfl_up_sync(0xffffffffu, incl, d);
        if (lane >= d) incl += u;
    }
    __shared__ int wsum[8];
    __shared__ int woff[8];
    if (lane == 31) wsum[wid] = incl;
    __syncthreads();
    if (t == 0) {
        int acc = 0;
#pragma unroll
        for (int i = 0; i < 8; i++) { woff[i] = acc; acc += wsum[i]; }
    }
    __syncthreads();
    int excl = incl - ts + woff[wid] + g_coff[blockIdx.x];
#pragma unroll
    for (int i = 0; i < 4; i++) {
        int idx = base + i;
        if (idx < N_NODES) { g_rowptr[idx] = excl; g_cursor[idx] = excl; }
        excl += c[i];
    }
}

__global__ void fill_kernel(const int* __restrict__ src, const int* __restrict__ dst, int E) {
    int e = blockIdx.x * blockDim.x + threadIdx.x;
    if (e < E) {
        int pos = atomicAdd(&g_cursor[dst[e]], 1);
        g_eidx[pos] = src[e];
    }
}

// prep: ws = colsum(W3), bsum = sum(b3)
__global__ void prep_kernel(const float* __restrict__ W3, const float* __restrict__ b3) {
    int t = threadIdx.x;  // 64
    float s = 0.f;
#pragma unroll
    for (int j = 0; j < D; j++) s += W3[j * D + t];
    g_ws[t] = s;
    if (t == 0) {
        float bs = 0.f;
#pragma unroll
        for (int j = 0; j < D; j++) bs += b3[j];
        g_bsum[0] = bs;
    }
}

// ============================ compute kernels ============================

// out[row] = in[row] @ W^T + b
__global__ __launch_bounds__(128) void gemm_kernel(const float* __restrict__ in,
                                                   const float* __restrict__ W,
                                                   const float* __restrict__ b,
                                                   float* __restrict__ out) {
    __shared__ float Ws[D * D];
    __shared__ float bs[D];
    int t = threadIdx.x;
    for (int i = t; i < D * D; i += 128) Ws[i] = W[i];
    if (t < D) bs[t] = b[t];
    __syncthreads();
    int row = blockIdx.x * 128 + t;
    if (row >= N_NODES) return;

    float4 h[16];
    const float4* inr = reinterpret_cast<const float4*>(in + (size_t)row * D);
#pragma unroll
    for (int i = 0; i < 16; i++) h[i] = inr[i];

    float4* outr = reinterpret_cast<float4*>(out + (size_t)row * D);
#pragma unroll
    for (int j4 = 0; j4 < 16; j4++) {
        float a0 = bs[j4 * 4 + 0], a1 = bs[j4 * 4 + 1], a2 = bs[j4 * 4 + 2], a3 = bs[j4 * 4 + 3];
        const float4* w0 = reinterpret_cast<const float4*>(Ws + (j4 * 4 + 0) * D);
        const float4* w1 = reinterpret_cast<const float4*>(Ws + (j4 * 4 + 1) * D);
        const float4* w2 = reinterpret_cast<const float4*>(Ws + (j4 * 4 + 2) * D);
        const float4* w3 = reinterpret_cast<const float4*>(Ws + (j4 * 4 + 3) * D);
#pragma unroll
        for (int kk = 0; kk < 16; kk++) {
            float4 hv = h[kk];
            float4 v0 = w0[kk], v1 = w1[kk], v2 = w2[kk], v3 = w3[kk];
            a0 += hv.x * v0.x + hv.y * v0.y + hv.z * v0.z + hv.w * v0.w;
            a1 += hv.x * v1.x + hv.y * v1.y + hv.z * v1.z + hv.w * v1.w;
            a2 += hv.x * v2.x + hv.y * v2.y + hv.z * v2.z + hv.w * v2.w;
            a3 += hv.x * v3.x + hv.y * v3.y + hv.z * v3.z + hv.w * v3.w;
        }
        outr[j4] = make_float4(a0, a1, a2, a3);
    }
}

// CSR gather: out[i] = tanh(sum over incoming edges of m[src])
// warp per node; lane l owns feature cols l, l+32. Broadcast index loads (no shfl),
// 4-edge unroll, 8 independent accumulators -> high MLP.
__global__ __launch_bounds__(256) void agg_kernel(const float* __restrict__ m,
                                                  float* __restrict__ out) {
    int node = (blockIdx.x * blockDim.x + threadIdx.x) >> 5;
    int l = threadIdx.x & 31;
    if (node >= N_NODES) return;
    int start = g_rowptr[node];
    int n = g_cnt[node];
    float a0 = 0.f, a1 = 0.f, b0 = 0.f, b1 = 0.f;
    float c0 = 0.f, c1 = 0.f, d0 = 0.f, d1 = 0.f;
    int k = 0;
    for (; k + 4 <= n; k += 4) {
        int s0 = __ldg(g_eidx + start + k + 0);
        int s1 = __ldg(g_eidx + start + k + 1);
        int s2 = __ldg(g_eidx + start + k + 2);
        int s3 = __ldg(g_eidx + start + k + 3);
        const float* r0 = m + (size_t)s0 * D;
        const float* r1 = m + (size_t)s1 * D;
        const float* r2 = m + (size_t)s2 * D;
        const float* r3 = m + (size_t)s3 * D;
        a0 += __ldg(r0 + l);      a1 += __ldg(r0 + l + 32);
        b0 += __ldg(r1 + l);      b1 += __ldg(r1 + l + 32);
        c0 += __ldg(r2 + l);      c1 += __ldg(r2 + l + 32);
        d0 += __ldg(r3 + l);      d1 += __ldg(r3 + l + 32);
    }
    for (; k < n; k++) {
        int s = __ldg(g_eidx + start + k);
        a0 += __ldg(m + (size_t)s * D + l);
        a1 += __ldg(m + (size_t)s * D + l + 32);
    }
    float v0 = (a0 + b0) + (c0 + d0);
    float v1 = (a1 + b1) + (c1 + d1);
    out[(size_t)node * D + l]      = tanhf(v0);
    out[(size_t)node * D + 32 + l] = tanhf(v1);
}

// Fused layer-2-agg + layer-3 collapse:
// r[i] = tanh(agg(m)[i]) . ws + bsum   (warp reduce over 64 features)
__global__ __launch_bounds__(256) void agg_rsum_kernel(const float* __restrict__ m) {
    int node = (blockIdx.x * blockDim.x + threadIdx.x) >> 5;
    int l = threadIdx.x & 31;
    if (node >= N_NODES) return;
    int start = g_rowptr[node];
    int n = g_cnt[node];
    float a0 = 0.f, a1 = 0.f, b0 = 0.f, b1 = 0.f;
    float c0 = 0.f, c1 = 0.f, d0 = 0.f, d1 = 0.f;
    int k = 0;
    for (; k + 4 <= n; k += 4) {
        int s0 = __ldg(g_eidx + start + k + 0);
        int s1 = __ldg(g_eidx + start + k + 1);
        int s2 = __ldg(g_eidx + start + k + 2);
        int s3 = __ldg(g_eidx + start + k + 3);
        const float* r0 = m + (size_t)s0 * D;
        const float* r1 = m + (size_t)s1 * D;
        const float* r2 = m + (size_t)s2 * D;
        const float* r3 = m + (size_t)s3 * D;
        a0 += __ldg(r0 + l);      a1 += __ldg(r0 + l + 32);
        b0 += __ldg(r1 + l);      b1 += __ldg(r1 + l + 32);
        c0 += __ldg(r2 + l);      c1 += __ldg(r2 + l + 32);
        d0 += __ldg(r3 + l);      d1 += __ldg(r3 + l + 32);
    }
    for (; k < n; k++) {
        int s = __ldg(g_eidx + start + k);
        a0 += __ldg(m + (size_t)s * D + l);
        a1 += __ldg(m + (size_t)s * D + l + 32);
    }
    float v0 = (a0 + b0) + (c0 + d0);
    float v1 = (a1 + b1) + (c1 + d1);
    float s = tanhf(v0) * g_ws[l] + tanhf(v1) * g_ws[l + 32];
#pragma unroll
    for (int off = 16; off; off >>= 1) s += __shfl_down_sync(0xffffffffu, s, off);
    if (l == 0) g_r[node] = s + g_bsum[0];
}

// final: per node, sum r over incoming edges (CSR), bin by graph
__global__ __launch_bounds__(256) void final_kernel(const int* __restrict__ n2g,
                                                    float* __restrict__ out) {
    __shared__ float bins[8];
    int t = threadIdx.x;
    if (t < 8) bins[t] = 0.f;
    __syncthreads();
    int node = (blockIdx.x * blockDim.x + t) >> 5;
    int l = t & 31;
    if (node < N_NODES) {
        int start = g_rowptr[node], n = g_cnt[node];
        float s = 0.f;
        for (int e = l; e < n; e += 32) s += __ldg(g_r + __ldg(g_eidx + start + e));
#pragma unroll
        for (int off = 16; off; off >>= 1) s += __shfl_down_sync(0xffffffffu, s, off);
        if (l == 0) atomicAdd(&bins[__ldg(n2g + node)], s);
    }
    __syncthreads();
    if (t < 8) atomicAdd(&out[t], bins[t]);
}

// ============================ launch ============================

extern "C" void kernel_launch(void* const* d_in, const int* in_sizes, int n_in,
                              void* d_out, int out_size) {
    const float* x   = (const float*)d_in[0];
    const float* W1  = (const float*)d_in[1];
    const float* b1  = (const float*)d_in[2];
    const float* W2  = (const float*)d_in[3];
    const float* b2  = (const float*)d_in[4];
    const float* W3  = (const float*)d_in[5];
    const float* b3  = (const float*)d_in[6];
    const int*   src = (const int*)d_in[7];
    const int*   dst = (const int*)d_in[8];
    const int*   n2g = (const int*)d_in[9];
    float* out = (float*)d_out;

    int E = in_sizes[7];

    int nb_nodes = (N_NODES + 255) / 256;
    int nb_edges = (E + 255) / 256;
    int gemm_blocks = (N_NODES + 127) / 128;
    int warp_blocks = (N_NODES * 32 + 255) / 256;   // warp per node

    float *bufA, *bufB;
    cudaGetSymbolAddress((void**)&bufA, g_bufA);
    cudaGetSymbolAddress((void**)&bufB, g_bufB);

    // --- CSR build (by dst) ---
    zero_cnt_kernel<<<nb_nodes, 256>>>();
    degree_kernel<<<nb_edges, 256>>>(dst, E);
    chunk_reduce_kernel<<<NCHUNK, 256>>>();
    chunk_scan_kernel<<<1, 128>>>(NCHUNK);
    chunk_apply_kernel<<<NCHUNK, 256>>>();
    fill_kernel<<<nb_edges, 256>>>(src, dst, E);
    prep_kernel<<<1, 64>>>(W3, b3);

    // --- layer 1: A = x@W1^T+b1 ; B = tanh(gather(A)) ---
    gemm_kernel<<<gemm_blocks, 128>>>(x, W1, b1, bufA);
    agg_kernel<<<warp_blocks, 256>>>(bufA, bufB);
    // --- layer 2: A = B@W2^T+b2 ; fused gather+tanh+layer3 collapse -> g_r ---
    gemm_kernel<<<gemm_blocks, 128>>>(bufB, W2, b2, bufA);
    agg_rsum_kernel<<<warp_blocks, 256>>>(bufA);
    // --- per-graph reduction ---
    cudaMemsetAsync(d_out, 0, (size_t)out_size * sizeof(float));
    final_kernel<<<warp_blocks, 256>>>(n2g, out);
}

// round 4
// speedup vs baseline: 27.4008x; 1.1641x over previous
#include <cuda_runtime.h>
#include <cuda_fp16.h>
#include <math.h>

#define N_NODES 100000
#define D 64
#define E_MAX 1600000
#define CHUNK 1024
#define NCHUNK ((N_NODES + CHUNK - 1) / CHUNK)   // 98

// ---- scratch (__device__ globals: allocation-free per harness rules) ----
__device__ __half g_mH[(size_t)N_NODES * D];    // fp16 message buffer (GEMM out)
__device__ float  g_h[(size_t)N_NODES * D];     // fp32 hidden state
__device__ float  g_r[N_NODES];                 // per-node scalar (layer-3 collapse)
__device__ float  g_ws[D];                      // colsum(W3)
__device__ float  g_bsum[1];                    // sum(b3)
__device__ int    g_cnt[N_NODES];
__device__ int    g_rowptr[N_NODES];
__device__ int    g_cursor[N_NODES];
__device__ int    g_eidx[E_MAX];
__device__ int    g_csum[128];                  // lookback publish slots (+1 encoded)

// ============================ init (fused) ============================
// block 0: ws/bsum/csum-zero/d_out-zero ; blocks 1..: zero g_cnt
__global__ void init_kernel(const float* __restrict__ W3, const float* __restrict__ b3,
                            float* __restrict__ out, int out_n) {
    int t = threadIdx.x;
    if (blockIdx.x == 0) {
        if (t < D) {
            float s = 0.f;
#pragma unroll
            for (int j = 0; j < D; j++) s += W3[j * D + t];
            g_ws[t] = s;
        } else if (t == D) {
            float bs = 0.f;
#pragma unroll
            for (int j = 0; j < D; j++) bs += b3[j];
            g_bsum[0] = bs;
        } else if (t >= 96 && t < 96 + out_n) {
            out[t - 96] = 0.f;
        } else if (t >= 128) {
            g_csum[t - 128] = 0;
        }
    } else {
        int i = (blockIdx.x - 1) * blockDim.x + t;
        if (i < N_NODES) g_cnt[i] = 0;
    }
}

__global__ void degree_kernel(const int* __restrict__ dst, int E) {
    int e = blockIdx.x * blockDim.x + threadIdx.x;
    if (e < E) atomicAdd(&g_cnt[dst[e]], 1);   // no return -> REDG
}

// single-pass exclusive scan over g_cnt with decoupled lookback.
// 98 blocks x 256 threads, 4 elems/thread. All blocks wave-1 resident.
__global__ __launch_bounds__(256) void scanapply_kernel() {
    int b = blockIdx.x, t = threadIdx.x;
    int base = b * CHUNK + t * 4;
    int c[4];
    int ts = 0;
#pragma unroll
    for (int i = 0; i < 4; i++) {
        int idx = base + i;
        c[i] = (idx < N_NODES) ? g_cnt[idx] : 0;
        ts += c[i];
    }
    int lane = t & 31, wid = t >> 5;
    int incl = ts;
#pragma unroll
    for (int d = 1; d < 32; d <<= 1) {
        int u = __shfl_up_sync(0xffffffffu, incl, d);
        if (lane >= d) incl += u;
    }
    __shared__ int wsum[8], woff[8];
    __shared__ int rsum[8];
    __shared__ int s_prefix;
    if (lane == 31) wsum[wid] = incl;
    __syncthreads();
    if (t == 0) {
        int acc = 0;
#pragma unroll
        for (int i = 0; i < 8; i++) { woff[i] = acc; acc += wsum[i]; }
        // publish this block's aggregate (+1 so 0 means "not ready")
        *(volatile int*)&g_csum[b] = acc + 1;
    }
    __syncthreads();
    // lookback: thread t (< b) spins on predecessor t's aggregate
    int part = 0;
    if (t < b) {
        volatile int* p = &g_csum[t];
        int v;
        do { v = *p; } while (v == 0);
        part = v - 1;
    }
#pragma unroll
    for (int off = 16; off; off >>= 1) part += __shfl_down_sync(0xffffffffu, part, off);
    if (lane == 0) rsum[wid] = part;
    __syncthreads();
    if (t == 0) {
        int acc = 0;
#pragma unroll
        for (int i = 0; i < 8; i++) acc += rsum[i];
        s_prefix = acc;
    }
    __syncthreads();
    int excl = incl - ts + woff[wid] + s_prefix;
#pragma unroll
    for (int i = 0; i < 4; i++) {
        int idx = base + i;
        if (idx < N_NODES) { g_rowptr[idx] = excl; g_cursor[idx] = excl; }
        excl += c[i];
    }
}

__global__ void fill_kernel(const int* __restrict__ src, const int* __restrict__ dst, int E) {
    int e = blockIdx.x * blockDim.x + threadIdx.x;
    if (e < E) {
        int pos = atomicAdd(&g_cursor[dst[e]], 1);
        g_eidx[pos] = src[e];
    }
}

// ============================ compute kernels ============================

// out[row] = in[row] @ W^T + b, written as fp16 (row = 32 half2 = 128B)
__global__ __launch_bounds__(128) void gemm_h_kernel(const float* __restrict__ in,
                                                     const float* __restrict__ W,
                                                     const float* __restrict__ b,
                                                     __half* __restrict__ out) {
    __shared__ float Ws[D * D];
    __shared__ float bs[D];
    int t = threadIdx.x;
    for (int i = t; i < D * D; i += 128) Ws[i] = W[i];
    if (t < D) bs[t] = b[t];
    __syncthreads();
    int row = blockIdx.x * 128 + t;
    if (row >= N_NODES) return;

    float4 h[16];
    const float4* inr = reinterpret_cast<const float4*>(in + (size_t)row * D);
#pragma unroll
    for (int i = 0; i < 16; i++) h[i] = inr[i];

    __half2 o[32];
#pragma unroll
    for (int j4 = 0; j4 < 16; j4++) {
        float a0 = bs[j4 * 4 + 0], a1 = bs[j4 * 4 + 1], a2 = bs[j4 * 4 + 2], a3 = bs[j4 * 4 + 3];
        const float4* w0 = reinterpret_cast<const float4*>(Ws + (j4 * 4 + 0) * D);
        const float4* w1 = reinterpret_cast<const float4*>(Ws + (j4 * 4 + 1) * D);
        const float4* w2 = reinterpret_cast<const float4*>(Ws + (j4 * 4 + 2) * D);
        const float4* w3 = reinterpret_cast<const float4*>(Ws + (j4 * 4 + 3) * D);
#pragma unroll
        for (int kk = 0; kk < 16; kk++) {
            float4 hv = h[kk];
            float4 v0 = w0[kk], v1 = w1[kk], v2 = w2[kk], v3 = w3[kk];
            a0 += hv.x * v0.x + hv.y * v0.y + hv.z * v0.z + hv.w * v0.w;
            a1 += hv.x * v1.x + hv.y * v1.y + hv.z * v1.z + hv.w * v1.w;
            a2 += hv.x * v2.x + hv.y * v2.y + hv.z * v2.z + hv.w * v2.w;
            a3 += hv.x * v3.x + hv.y * v3.y + hv.z * v3.z + hv.w * v3.w;
        }
        o[j4 * 2 + 0] = __floats2half2_rn(a0, a1);
        o[j4 * 2 + 1] = __floats2half2_rn(a2, a3);
    }
    uint4* outr = reinterpret_cast<uint4*>(out + (size_t)row * D);
    const uint4* ov = reinterpret_cast<const uint4*>(o);
#pragma unroll
    for (int i = 0; i < 8; i++) outr[i] = ov[i];
}

// CSR gather on fp16 messages: out[i] = tanh(sum_in m[src]) (fp32 accumulation)
// warp per node; lane l owns cols 2l, 2l+1 (one half2 per edge -> 128B/warp coalesced)
__global__ __launch_bounds__(256) void agg_kernel(const __half2* __restrict__ m,
                                                  float* __restrict__ out) {
    int node = (blockIdx.x * blockDim.x + threadIdx.x) >> 5;
    int l = threadIdx.x & 31;
    if (node >= N_NODES) return;
    int start = g_rowptr[node];
    int n = g_cnt[node];
    float a0 = 0.f, a1 = 0.f, b0 = 0.f, b1 = 0.f;
    float c0 = 0.f, c1 = 0.f, d0 = 0.f, d1 = 0.f;
    int k = 0;
    for (; k + 4 <= n; k += 4) {
        int s0 = __ldg(g_eidx + start + k + 0);
        int s1 = __ldg(g_eidx + start + k + 1);
        int s2 = __ldg(g_eidx + start + k + 2);
        int s3 = __ldg(g_eidx + start + k + 3);
        float2 v0 = __half22float2(__ldg(m + (size_t)s0 * 32 + l));
        float2 v1 = __half22float2(__ldg(m + (size_t)s1 * 32 + l));
        float2 v2 = __half22float2(__ldg(m + (size_t)s2 * 32 + l));
        float2 v3 = __half22float2(__ldg(m + (size_t)s3 * 32 + l));
        a0 += v0.x; a1 += v0.y;
        b0 += v1.x; b1 += v1.y;
        c0 += v2.x; c1 += v2.y;
        d0 += v3.x; d1 += v3.y;
    }
    for (; k < n; k++) {
        int s = __ldg(g_eidx + start + k);
        float2 v = __half22float2(__ldg(m + (size_t)s * 32 + l));
        a0 += v.x; a1 += v.y;
    }
    float v0 = (a0 + b0) + (c0 + d0);
    float v1 = (a1 + b1) + (c1 + d1);
    float2 r = make_float2(tanhf(v0), tanhf(v1));
    reinterpret_cast<float2*>(out + (size_t)node * D)[l] = r;
}

// Fused layer-2 gather + tanh + layer-3 collapse: r[i] = tanh(agg)[i] . ws + bsum
__global__ __launch_bounds__(256) void agg_rsum_kernel(const __half2* __restrict__ m) {
    int node = (blockIdx.x * blockDim.x + threadIdx.x) >> 5;
    int l = threadIdx.x & 31;
    if (node >= N_NODES) return;
    int start = g_rowptr[node];
    int n = g_cnt[node];
    float a0 = 0.f, a1 = 0.f, b0 = 0.f, b1 = 0.f;
    float c0 = 0.f, c1 = 0.f, d0 = 0.f, d1 = 0.f;
    int k = 0;
    for (; k + 4 <= n; k += 4) {
        int s0 = __ldg(g_eidx + start + k + 0);
        int s1 = __ldg(g_eidx + start + k + 1);
        int s2 = __ldg(g_eidx + start + k + 2);
        int s3 = __ldg(g_eidx + start + k + 3);
        float2 v0 = __half22float2(__ldg(m + (size_t)s0 * 32 + l));
        float2 v1 = __half22float2(__ldg(m + (size_t)s1 * 32 + l));
        float2 v2 = __half22float2(__ldg(m + (size_t)s2 * 32 + l));
        float2 v3 = __half22float2(__ldg(m + (size_t)s3 * 32 + l));
        a0 += v0.x; a1 += v0.y;
        b0 += v1.x; b1 += v1.y;
        c0 += v2.x; c1 += v2.y;
        d0 += v3.x; d1 += v3.y;
    }
    for (; k < n; k++) {
        int s = __ldg(g_eidx + start + k);
        float2 v = __half22float2(__ldg(m + (size_t)s * 32 + l));
        a0 += v.x; a1 += v.y;
    }
    float v0 = (a0 + b0) + (c0 + d0);
    float v1 = (a1 + b1) + (c1 + d1);
    float s = tanhf(v0) * g_ws[2 * l] + tanhf(v1) * g_ws[2 * l + 1];
#pragma unroll
    for (int off = 16; off; off >>= 1) s += __shfl_down_sync(0xffffffffu, s, off);
    if (l == 0) g_r[node] = s + g_bsum[0];
}

// final: per node, sum r over incoming edges (CSR), bin by graph
__global__ __launch_bounds__(256) void final_kernel(const int* __restrict__ n2g,
                                                    float* __restrict__ out) {
    __shared__ float bins[8];
    int t = threadIdx.x;
    if (t < 8) bins[t] = 0.f;
    __syncthreads();
    int node = (blockIdx.x * blockDim.x + t) >> 5;
    int l = t & 31;
    if (node < N_NODES) {
        int start = g_rowptr[node], n = g_cnt[node];
        float s = 0.f;
        for (int e = l; e < n; e += 32) s += __ldg(g_r + __ldg(g_eidx + start + e));
#pragma unroll
        for (int off = 16; off; off >>= 1) s += __shfl_down_sync(0xffffffffu, s, off);
        if (l == 0) atomicAdd(&bins[__ldg(n2g + node)], s);
    }
    __syncthreads();
    if (t < 8) atomicAdd(&out[t], bins[t]);
}

// ============================ launch ============================

extern "C" void kernel_launch(void* const* d_in, const int* in_sizes, int n_in,
                              void* d_out, int out_size) {
    const float* x   = (const float*)d_in[0];
    const float* W1  = (const float*)d_in[1];
    const float* b1  = (const float*)d_in[2];
    const float* W2  = (const float*)d_in[3];
    const float* b2  = (const float*)d_in[4];
    const float* W3  = (const float*)d_in[5];
    const float* b3  = (const float*)d_in[6];
    const int*   src = (const int*)d_in[7];
    const int*   dst = (const int*)d_in[8];
    const int*   n2g = (const int*)d_in[9];
    float* out = (float*)d_out;

    int E = in_sizes[7];

    int nb_edges = (E + 255) / 256;
    int gemm_blocks = (N_NODES + 127) / 128;
    int warp_blocks = (N_NODES * 32 + 255) / 256;   // warp per node
    int init_blocks = 1 + (N_NODES + 255) / 256;

    __half* mH;  float* h;
    cudaGetSymbolAddress((void**)&mH, g_mH);
    cudaGetSymbolAddress((void**)&h,  g_h);

    // CSR build + constants (5 launches)
    init_kernel<<<init_blocks, 256>>>(W3, b3, out, out_size);
    degree_kernel<<<nb_edges, 256>>>(dst, E);
    scanapply_kernel<<<NCHUNK, 256>>>();
    fill_kernel<<<nb_edges, 256>>>(src, dst, E);

    // layer 1
    gemm_h_kernel<<<gemm_blocks, 128>>>(x, W1, b1, mH);
    agg_kernel<<<warp_blocks, 256>>>((const __half2*)mH, h);
    // layer 2 + collapsed layer 3
    gemm_h_kernel<<<gemm_blocks, 128>>>(h, W2, b2, mH);
    agg_rsum_kernel<<<warp_blocks, 256>>>((const __half2*)mH);
    // per-graph reduction
    final_kernel<<<warp_blocks, 256>>>(n2g, out);
}

// round 5
// speedup vs baseline: 32.4957x; 1.1859x over previous
#include <cuda_runtime.h>
#include <cuda_fp16.h>
#include <math.h>

#define N_NODES 100000
#define D 64
#define E_MAX 1600000
#define CHUNK 1024
#define NCHUNK ((N_NODES + CHUNK - 1) / CHUNK)   // 98

// ---- scratch (__device__ globals: allocation-free per harness rules) ----
__device__ __half g_mH[(size_t)N_NODES * D];    // fp16 message buffer (GEMM out)
__device__ __half g_hH[(size_t)N_NODES * D];    // fp16 hidden state
__device__ float  g_r[N_NODES];                 // per-node scalar (layer-3 collapse)
__device__ float  g_ws[D];                      // colsum(W3)
__device__ float  g_bsum[1];                    // sum(b3)
__device__ int    g_cnt[N_NODES];
__device__ int    g_rowptr[N_NODES];
__device__ int    g_cursor[N_NODES];
__device__ int    g_eidx[E_MAX];
__device__ int    g_csum[128];                  // lookback publish slots (+1 encoded)

// ---- side stream + events for graph fork (created at load, before harness
// mem checkpoints; never freed; no per-call allocation) ----
static cudaStream_t g_s2;
static cudaEvent_t  g_evFork, g_evJoin;
static bool g_streamOk = [](){
    if (cudaStreamCreateWithFlags(&g_s2, cudaStreamNonBlocking) != cudaSuccess) return false;
    if (cudaEventCreateWithFlags(&g_evFork, cudaEventDisableTiming) != cudaSuccess) return false;
    if (cudaEventCreateWithFlags(&g_evJoin, cudaEventDisableTiming) != cudaSuccess) return false;
    return true;
}();

// ============================ init (fused) ============================
__global__ void init_kernel(const float* __restrict__ W3, const float* __restrict__ b3,
                            float* __restrict__ out, int out_n) {
    int t = threadIdx.x;
    if (blockIdx.x == 0) {
        if (t < D) {
            float s = 0.f;
#pragma unroll
            for (int j = 0; j < D; j++) s += W3[j * D + t];
            g_ws[t] = s;
        } else if (t == D) {
            float bs = 0.f;
#pragma unroll
            for (int j = 0; j < D; j++) bs += b3[j];
            g_bsum[0] = bs;
        } else if (t >= 96 && t < 96 + out_n) {
            out[t - 96] = 0.f;
        } else if (t >= 128) {
            g_csum[t - 128] = 0;
        }
    } else {
        int i = (blockIdx.x - 1) * blockDim.x + t;
        if (i < N_NODES) g_cnt[i] = 0;
    }
}

__global__ void degree_kernel(const int* __restrict__ dst, int E) {
    int e = blockIdx.x * blockDim.x + threadIdx.x;
    if (e < E) atomicAdd(&g_cnt[dst[e]], 1);   // no return -> REDG
}

// single-pass exclusive scan with decoupled lookback (98 blocks, wave-1 resident)
__global__ __launch_bounds__(256) void scanapply_kernel() {
    int b = blockIdx.x, t = threadIdx.x;
    int base = b * CHUNK + t * 4;
    int c[4];
    int ts = 0;
#pragma unroll
    for (int i = 0; i < 4; i++) {
        int idx = base + i;
        c[i] = (idx < N_NODES) ? g_cnt[idx] : 0;
        ts += c[i];
    }
    int lane = t & 31, wid = t >> 5;
    int incl = ts;
#pragma unroll
    for (int d = 1; d < 32; d <<= 1) {
        int u = __shfl_up_sync(0xffffffffu, incl, d);
        if (lane >= d) incl += u;
    }
    __shared__ int wsum[8], woff[8];
    __shared__ int rsum[8];
    __shared__ int s_prefix;
    if (lane == 31) wsum[wid] = incl;
    __syncthreads();
    if (t == 0) {
        int acc = 0;
#pragma unroll
        for (int i = 0; i < 8; i++) { woff[i] = acc; acc += wsum[i]; }
        *(volatile int*)&g_csum[b] = acc + 1;   // publish (+1: 0 = not ready)
    }
    __syncthreads();
    int part = 0;
    if (t < b) {
        volatile int* p = &g_csum[t];
        int v;
        do { v = *p; } while (v == 0);
        part = v - 1;
    }
#pragma unroll
    for (int off = 16; off; off >>= 1) part += __shfl_down_sync(0xffffffffu, part, off);
    if (lane == 0) rsum[wid] = part;
    __syncthreads();
    if (t == 0) {
        int acc = 0;
#pragma unroll
        for (int i = 0; i < 8; i++) acc += rsum[i];
        s_prefix = acc;
    }
    __syncthreads();
    int excl = incl - ts + woff[wid] + s_prefix;
#pragma unroll
    for (int i = 0; i < 4; i++) {
        int idx = base + i;
        if (idx < N_NODES) { g_rowptr[idx] = excl; g_cursor[idx] = excl; }
        excl += c[i];
    }
}

__global__ void fill_kernel(const int* __restrict__ src, const int* __restrict__ dst, int E) {
    int e = blockIdx.x * blockDim.x + threadIdx.x;
    if (e < E) {
        int pos = atomicAdd(&g_cursor[dst[e]], 1);
        g_eidx[pos] = src[e];
    }
}

// ============================ register-blocked GEMM ============================
// out[row] = in[row] @ W^T + b, fp16 output.
// 256 threads, 128 rows x 64 cols per block; thread = 4 rows x 8 cols.
// Input staged TRANSPOSED in smem: k-loop = 1 LDS.128 + 8 broadcast LDS per 32 FFMA.
template<bool HALF_IN>
__global__ __launch_bounds__(256) void gemm_rb_kernel(const void* __restrict__ in_,
                                                      const float* __restrict__ W,
                                                      const float* __restrict__ b,
                                                      __half2* __restrict__ out) {
    __shared__ float inT[D][128];   // 32KB, [k][row]
    __shared__ float Ws[D * D];     // 16KB
    __shared__ float bs[D];
    int t = threadIdx.x;
    for (int i = t; i < D * D; i += 256) Ws[i] = W[i];
    if (t < D) bs[t] = b[t];

    int row0 = blockIdx.x * 128;
    int r = t >> 1, half = t & 1;          // r: 0..127, half: which 32 cols
    int grow = row0 + r;
    if (HALF_IN) {
        const __half2* inH = (const __half2*)in_ + (size_t)grow * 32 + half * 16;
        if (grow < N_NODES) {
#pragma unroll
            for (int i = 0; i < 16; i++) {
                float2 f = __half22float2(inH[i]);
                inT[half * 32 + 2 * i + 0][r] = f.x;
                inT[half * 32 + 2 * i + 1][r] = f.y;
            }
        } else {
#pragma unroll
            for (int i = 0; i < 32; i++) inT[half * 32 + i][r] = 0.f;
        }
    } else {
        const float4* inF = (const float4*)((const float*)in_ + (size_t)grow * D + half * 32);
        if (grow < N_NODES) {
#pragma unroll
            for (int i = 0; i < 8; i++) {
                float4 v = inF[i];
                inT[half * 32 + 4 * i + 0][r] = v.x;
                inT[half * 32 + 4 * i + 1][r] = v.y;
                inT[half * 32 + 4 * i + 2][r] = v.z;
                inT[half * 32 + 4 * i + 3][r] = v.w;
            }
        } else {
#pragma unroll
            for (int i = 0; i < 32; i++) inT[half * 32 + i][r] = 0.f;
        }
    }
    __syncthreads();

    int w = t >> 5, l = t & 31;
    int colBase = w * 8;
    float acc[4][8];
#pragma unroll
    for (int i = 0; i < 4; i++)
#pragma unroll
        for (int j = 0; j < 8; j++) acc[i][j] = 0.f;

#pragma unroll 4
    for (int k = 0; k < D; k++) {
        float4 a = *(const float4*)&inT[k][l * 4];
#pragma unroll
        for (int jj = 0; jj < 8; jj++) {
            float wv = Ws[(colBase + jj) * D + k];
            acc[0][jj] += a.x * wv;
            acc[1][jj] += a.y * wv;
            acc[2][jj] += a.z * wv;
            acc[3][jj] += a.w * wv;
        }
    }

#pragma unroll
    for (int i = 0; i < 4; i++) {
        int orow = row0 + l * 4 + i;
        if (orow < N_NODES) {
            __half2 o[4];
#pragma unroll
            for (int j = 0; j < 4; j++)
                o[j] = __floats2half2_rn(acc[i][2 * j]     + bs[colBase + 2 * j],
                                         acc[i][2 * j + 1] + bs[colBase + 2 * j + 1]);
            *(uint4*)&out[(size_t)orow * 32 + colBase / 2] = *(const uint4*)o;
        }
    }
}

// ============================ aggregation kernels ============================

// CSR gather on fp16 messages: out[i] = tanh(sum_in m[src]) (fp32 accum, fp16 store)
__global__ __launch_bounds__(256) void agg_kernel(const __half2* __restrict__ m,
                                                  __half2* __restrict__ out) {
    int node = (blockIdx.x * blockDim.x + threadIdx.x) >> 5;
    int l = threadIdx.x & 31;
    if (node >= N_NODES) return;
    int start = g_rowptr[node];
    int n = g_cnt[node];
    float a0 = 0.f, a1 = 0.f, b0 = 0.f, b1 = 0.f;
    float c0 = 0.f, c1 = 0.f, d0 = 0.f, d1 = 0.f;
    int k = 0;
    for (; k + 4 <= n; k += 4) {
        int s0 = __ldg(g_eidx + start + k + 0);
        int s1 = __ldg(g_eidx + start + k + 1);
        int s2 = __ldg(g_eidx + start + k + 2);
        int s3 = __ldg(g_eidx + start + k + 3);
        float2 v0 = __half22float2(__ldg(m + (size_t)s0 * 32 + l));
        float2 v1 = __half22float2(__ldg(m + (size_t)s1 * 32 + l));
        float2 v2 = __half22float2(__ldg(m + (size_t)s2 * 32 + l));
        float2 v3 = __half22float2(__ldg(m + (size_t)s3 * 32 + l));
        a0 += v0.x; a1 += v0.y;
        b0 += v1.x; b1 += v1.y;
        c0 += v2.x; c1 += v2.y;
        d0 += v3.x; d1 += v3.y;
    }
    for (; k < n; k++) {
        int s = __ldg(g_eidx + start + k);
        float2 v = __half22float2(__ldg(m + (size_t)s * 32 + l));
        a0 += v.x; a1 += v.y;
    }
    float v0 = (a0 + b0) + (c0 + d0);
    float v1 = (a1 + b1) + (c1 + d1);
    out[(size_t)node * 32 + l] = __floats2half2_rn(tanhf(v0), tanhf(v1));
}

// Fused layer-2 gather + tanh + layer-3 collapse: r[i] = tanh(agg)[i] . ws + bsum
__global__ __launch_bounds__(256) void agg_rsum_kernel(const __half2* __restrict__ m) {
    int node = (blockIdx.x * blockDim.x + threadIdx.x) >> 5;
    int l = threadIdx.x & 31;
    if (node >= N_NODES) return;
    int start = g_rowptr[node];
    int n = g_cnt[node];
    float a0 = 0.f, a1 = 0.f, b0 = 0.f, b1 = 0.f;
    float c0 = 0.f, c1 = 0.f, d0 = 0.f, d1 = 0.f;
    int k = 0;
    for (; k + 4 <= n; k += 4) {
        int s0 = __ldg(g_eidx + start + k + 0);
        int s1 = __ldg(g_eidx + start + k + 1);
        int s2 = __ldg(g_eidx + start + k + 2);
        int s3 = __ldg(g_eidx + start + k + 3);
        float2 v0 = __half22float2(__ldg(m + (size_t)s0 * 32 + l));
        float2 v1 = __half22float2(__ldg(m + (size_t)s1 * 32 + l));
        float2 v2 = __half22float2(__ldg(m + (size_t)s2 * 32 + l));
        float2 v3 = __half22float2(__ldg(m + (size_t)s3 * 32 + l));
        a0 += v0.x; a1 += v0.y;
        b0 += v1.x; b1 += v1.y;
        c0 += v2.x; c1 += v2.y;
        d0 += v3.x; d1 += v3.y;
    }
    for (; k < n; k++) {
        int s = __ldg(g_eidx + start + k);
        float2 v = __half22float2(__ldg(m + (size_t)s * 32 + l));
        a0 += v.x; a1 += v.y;
    }
    float v0 = (a0 + b0) + (c0 + d0);
    float v1 = (a1 + b1) + (c1 + d1);
    float s = tanhf(v0) * g_ws[2 * l] + tanhf(v1) * g_ws[2 * l + 1];
#pragma unroll
    for (int off = 16; off; off >>= 1) s += __shfl_down_sync(0xffffffffu, s, off);
    if (l == 0) g_r[node] = s + g_bsum[0];
}

// final: per node, sum r over incoming edges (CSR), bin by graph
__global__ __launch_bounds__(256) void final_kernel(const int* __restrict__ n2g,
                                                    float* __restrict__ out) {
    __shared__ float bins[8];
    int t = threadIdx.x;
    if (t < 8) bins[t] = 0.f;
    __syncthreads();
    int node = (blockIdx.x * blockDim.x + t) >> 5;
    int l = t & 31;
    if (node < N_NODES) {
        int start = g_rowptr[node], n = g_cnt[node];
        float s = 0.f;
        for (int e = l; e < n; e += 32) s += __ldg(g_r + __ldg(g_eidx + start + e));
#pragma unroll
        for (int off = 16; off; off >>= 1) s += __shfl_down_sync(0xffffffffu, s, off);
        if (l == 0) atomicAdd(&bins[__ldg(n2g + node)], s);
    }
    __syncthreads();
    if (t < 8) atomicAdd(&out[t], bins[t]);
}

// ============================ launch ============================

extern "C" void kernel_launch(void* const* d_in, const int* in_sizes, int n_in,
                              void* d_out, int out_size) {
    const float* x   = (const float*)d_in[0];
    const float* W1  = (const float*)d_in[1];
    const float* b1  = (const float*)d_in[2];
    const float* W2  = (const float*)d_in[3];
    const float* b2  = (const float*)d_in[4];
    const float* W3  = (const float*)d_in[5];
    const float* b3  = (const float*)d_in[6];
    const int*   src = (const int*)d_in[7];
    const int*   dst = (const int*)d_in[8];
    const int*   n2g = (const int*)d_in[9];
    float* out = (float*)d_out;

    int E = in_sizes[7];

    int nb_edges = (E + 255) / 256;
    int gemm_blocks = (N_NODES + 127) / 128;
    int warp_blocks = (N_NODES * 32 + 255) / 256;
    int init_blocks = 1 + (N_NODES + 255) / 256;

    __half* mH;  __half* hH;
    cudaGetSymbolAddress((void**)&mH, g_mH);
    cudaGetSymbolAddress((void**)&hH, g_hH);

    if (g_streamOk) {
        // fork: gemm1 on side stream, CSR build on main stream
        cudaEventRecord(g_evFork, 0);
        cudaStreamWaitEvent(g_s2, g_evFork, 0);
        gemm_rb_kernel<false><<<gemm_blocks, 256, 0, g_s2>>>(x, W1, b1, (__half2*)mH);
        cudaEventRecord(g_evJoin, g_s2);

        init_kernel<<<init_blocks, 256>>>(W3, b3, out, out_size);
        degree_kernel<<<nb_edges, 256>>>(dst, E);
        scanapply_kernel<<<NCHUNK, 256>>>();
        fill_kernel<<<nb_edges, 256>>>(src, dst, E);

        cudaStreamWaitEvent(0, g_evJoin, 0);   // join before agg1
    } else {
        init_kernel<<<init_blocks, 256>>>(W3, b3, out, out_size);
        degree_kernel<<<nb_edges, 256>>>(dst, E);
        scanapply_kernel<<<NCHUNK, 256>>>();
        fill_kernel<<<nb_edges, 256>>>(src, dst, E);
        gemm_rb_kernel<false><<<gemm_blocks, 256>>>(x, W1, b1, (__half2*)mH);
    }

    agg_kernel<<<warp_blocks, 256>>>((const __half2*)mH, (__half2*)hH);
    gemm_rb_kernel<true><<<gemm_blocks, 256>>>(hH, W2, b2, (__half2*)mH);
    agg_rsum_kernel<<<warp_blocks, 256>>>((const __half2*)mH);
    final_kernel<<<warp_blocks, 256>>>(n2g, out);
}